// round 8
// baseline (speedup 1.0000x reference)
#include <cuda_runtime.h>
#include <math.h>

#define CC 31
#define HO 256
#define WO 256
#define NPIX (HO*WO)          // 65536
#define HI 128
#define WI 128

// ============================ single fused kernel ============================
// Phase A: per-block redundant precompute (all in smem, no global scratch),
//          with slot-dedup + tight-bound class-table build.
// Phase B: bilinear + exact boundary-aware 9x5x5 conv + residual + 31x31 mix.
#define TROWS 12
#define TS (TROWS*36)
#define TILE_F (CC*TS)        // 13392
#define WCLS_F (4*5*225)      // 4500
#define MROW   32
#define MPS_F  (4*31*MROW)    // 3968
#define SMEM_F (TILE_F + WCLS_F + MPS_F + 8)

// scratch offsets inside tile region (Phase A only; max 9001 < TILE_F)
#define SCR_BW2 0             // 4096
#define SCR_WEM 4096          // 1440
#define SCR_WCM 5536          // 1440
#define SCR_G2  6976          // 2025

__global__ __launch_bounds__(256, 2) void kall(
    const float* __restrict__ x,
    const float* __restrict__ WE,  // (4,32,1,5,3,3) = 4*1440
    const float* __restrict__ WC,  // (4,1,32,5,3,3)
    const float* __restrict__ W2,  // (4,31,31) = 4*961
    const float* __restrict__ bw1, const float* __restrict__ bb1,
    const float* __restrict__ bw2, const float* __restrict__ bb2,
    const float* __restrict__ r2w, const float* __restrict__ r2b,
    const float* __restrict__ ow,  const float* __restrict__ ob,
    const float* __restrict__ l1w, const float* __restrict__ l1b,
    const float* __restrict__ l2w, const float* __restrict__ l2b,
    float* __restrict__ out)
{
    extern __shared__ float sm[];
    float* tile = sm;
    float* wcls = sm + TILE_F;
    float* Mps  = sm + TILE_F + WCLS_F;
    float* offs = Mps + MPS_F;

    __shared__ float s_bw1[192], s_bb1[64], s_bb2[64];
    __shared__ float s_r2w[256], s_r2b[4], s_ow[128], s_ob[2];
    __shared__ float s_l1w[128], s_l1b[64], s_l2w[256], s_l2b[4];
    __shared__ float e1s[4][64], e2s[4][64];
    __shared__ float h1s[2][64], lgs[2][4];
    __shared__ float r2s[4][4], rsum_s[4];

    int tx = threadIdx.x, ty = threadIdx.y;
    int tid = ty*32 + tx;

    // ======================= Phase A: precompute =======================
    // A0: stage weights
    for (int t = tid; t < 4096; t += 256) tile[SCR_BW2 + t] = bw2[t];
    for (int t = tid; t < 192;  t += 256) s_bw1[t] = bw1[t];
    for (int t = tid; t < 64;   t += 256) { s_bb1[t] = bb1[t]; s_bb2[t] = bb2[t];
                                            s_l1b[t] = l1b[t]; }
    for (int t = tid; t < 256;  t += 256) { s_r2w[t] = r2w[t]; s_l2w[t] = l2w[t]; }
    for (int t = tid; t < 128;  t += 256) { s_ow[t] = ow[t]; s_l1w[t] = l1w[t]; }
    if (tid < 4) { s_r2b[tid] = r2b[tid]; s_l2b[tid] = l2b[tid]; }
    if (tid < 2) s_ob[tid] = ob[tid];
    __syncthreads();

    // A1: parity MLP layer1 + routing h1
    {
        int p = tid >> 6, o = tid & 63;
        float ch = (p & 2) ? 0.25f : -0.25f;
        float cw = (p & 1) ? 0.25f : -0.25f;
        float a = s_bw1[o*3+0]*0.5f + s_bw1[o*3+1]*ch + s_bw1[o*3+2]*cw + s_bb1[o];
        e1s[p][o] = a > 0.f ? a : 0.f;
    }
    if (tid < 128) {
        int r = tid >> 6, o = tid & 63;
        float chr = r ? 0.25f : -0.25f;
        float a = s_l1w[o*2+0]*0.5f + s_l1w[o*2+1]*chr + s_l1b[o];
        h1s[r][o] = a > 0.f ? a : 0.f;
    }
    __syncthreads();

    // A2: layer2 + routing logits
    {
        int p = tid >> 6, o = tid & 63;
        float a = s_bb2[o];
        #pragma unroll 8
        for (int i = 0; i < 64; i++) a += tile[SCR_BW2 + o*64+i]*e1s[p][i];
        e2s[p][o] = a > 0.f ? a : 0.f;
    }
    if (tid < 8) {
        int r = tid >> 2, e = tid & 3;
        float a = s_l2b[e];
        #pragma unroll 8
        for (int o = 0; o < 64; o++) a += s_l2w[e*64+o]*h1s[r][o];
        lgs[r][e] = a;
    }
    __syncthreads();

    // A3: heads (offsets + routing2) and rsum
    if (tid < 24) {
        int p = tid / 6, u = tid % 6;
        if (u < 2) {
            float a = s_ob[u];
            for (int i = 0; i < 64; i++) a += s_ow[u*64+i]*e2s[p][i];
            offs[p*2+u] = a;
        } else {
            int e = u - 2;
            float a = s_r2b[e];
            for (int i = 0; i < 64; i++) a += s_r2w[e*64+i]*e2s[p][i];
            r2s[p][e] = 1.f/(1.f+expf(-a));
        }
    }
    if (tid >= 32 && tid < 36) {
        int e = tid - 32;
        float rsv = 0.f;
        #pragma unroll
        for (int r = 0; r < 2; r++) {
            float m = fmaxf(fmaxf(lgs[r][0], lgs[r][1]), fmaxf(lgs[r][2], lgs[r][3]));
            float s = 0.f;
            #pragma unroll
            for (int j = 0; j < 4; j++) s += expf(lgs[r][j]-m);
            rsv += expf(lgs[r][e]-m)/s;
        }
        rsum_s[e] = rsv;
    }
    __syncthreads();

    // A4: rsum-mixed conv weights
    {
        float r0 = rsum_s[0], r1 = rsum_s[1], r2 = rsum_s[2], r3 = rsum_s[3];
        for (int idx = tid; idx < 32*45; idx += 256) {
            tile[SCR_WEM + idx] = r0*__ldg(WE+idx) + r1*__ldg(WE+1440+idx)
                                + r2*__ldg(WE+2880+idx) + r3*__ldg(WE+4320+idx);
            tile[SCR_WCM + idx] = r0*__ldg(WC+idx) + r1*__ldg(WC+1440+idx)
                                + r2*__ldg(WC+2880+idx) + r3*__ldg(WC+4320+idx);
        }
    }
    __syncthreads();

    // A5: G2[q][r] = sum_k wcm[k][q]*wem[k][r]
    for (int idx = tid; idx < 45*45; idx += 256) {
        int q = idx / 45, r = idx % 45;
        float a0 = 0.f, a1 = 0.f;
        #pragma unroll
        for (int k = 0; k < 32; k += 2) {
            a0 += tile[SCR_WCM + k*45+q]*tile[SCR_WEM + k*45+r];
            a1 += tile[SCR_WCM + (k+1)*45+q]*tile[SCR_WEM + (k+1)*45+r];
        }
        tile[SCR_G2 + idx] = a0 + a1;
    }
    __syncthreads();

    // A6: boundary-class kernels (slot-dedup + tight bounds) + mix matrices
    int oylo = blockIdx.y*8, oxlo = blockIdx.x*32;
    int yec = (oylo == 0) ? 1 : ((oylo + 7 >= HO-1) ? 2 : 0);
    int xec = (oxlo == 0) ? 1 : ((oxlo + 31 >= WO-1) ? 2 : 0);

    // per-class q-ranges
    // zc: 0->d=0 [2,4], 1->d=1 [1,4], 2->int [0,4], 3->d=29 [0,3], 4->d=30 [0,2]
    const int qzl_t[5] = {2,1,0,0,0}, qzh_t[5] = {4,4,4,3,2};
    // y/x class: 0 interior [0,2], 1 low edge [1,2], 2 high edge [0,1]
    const int q3l_t[3] = {0,1,0}, q3h_t[3] = {2,2,1};

    // slots needed: 0 always; 1 if y-edge; 2 if x-edge; 3 if both
    int slot_mask = 1 | ((yec ? 1 : 0) << 1) | ((xec ? 1 : 0) << 2)
                  | (((yec && xec) ? 1 : 0) << 3);

    #pragma unroll 1
    for (int slot = 0; slot < 4; slot++) {
        if (!((slot_mask >> slot) & 1)) continue;
        int ys = (slot & 1) ? yec : 0;
        int xs = (slot & 2) ? xec : 0;
        int qyl_c = q3l_t[ys], qyh_c = q3h_t[ys];
        int qxl_c = q3l_t[xs], qxh_c = q3h_t[xs];
        for (int t = tid; t < 1125; t += 256) {
            int zc = t / 225, s = t % 225;
            int sz = s / 25, sy = (s % 25) / 5, sx = s % 5;
            int qzl = max(qzl_t[zc], sz-4), qzh = min(qzh_t[zc], sz);
            int qyl = max(qyl_c, sy-2),     qyh = min(qyh_c, sy);
            int qxl = max(qxl_c, sx-2),     qxh = min(qxh_c, sx);
            float acc = 0.f;
            for (int qz = qzl; qz <= qzh; qz++) {
                const float* Gz = tile + SCR_G2 + qz*9*45 + (sz-qz)*9;
                for (int qy = qyl; qy <= qyh; qy++) {
                    const float* Gy = Gz + qy*3*45 + (sy-qy)*3;
                    for (int qx = qxl; qx <= qxh; qx++)
                        acc += Gy[qx*45 + (sx-qx)];
                }
            }
            wcls[slot*1125 + t] = acc;
        }
    }
    for (int t = tid; t < MPS_F; t += 256) {
        int p = t / (31*MROW), r = t % (31*MROW);
        int ii = r / MROW, jj = r % MROW;
        float v = 0.f;
        if (jj < 31) {
            int ij = ii*31 + jj;
            v = r2s[p][0]*__ldg(W2+ij) + r2s[p][1]*__ldg(W2+961+ij)
              + r2s[p][2]*__ldg(W2+2*961+ij) + r2s[p][3]*__ldg(W2+3*961+ij);
        }
        Mps[t] = v;
    }
    __syncthreads();   // Phase A complete; tile scratch may now be overwritten

    // ======================= Phase B =======================
    int gx0 = blockIdx.x*32 - 2, gy0 = blockIdx.y*8 - 2;

    // bilinear halo tile from x
    for (int t = tid; t < TROWS*36; t += 256) {
        int yy = t / 36, xx = t % 36;
        int gy = gy0 + yy, gx = gx0 + xx;
        if (gy < 0 || gy >= HO || gx < 0 || gx >= WO) {
            #pragma unroll 4
            for (int c = 0; c < CC; c++) tile[c*TS + t] = 0.f;
        } else {
            int p = ((gy & 1) << 1) | (gx & 1);
            float ix = (gx + 0.5f)*0.5f - 0.5f + offs[p*2+0];
            float iy = (gy + 0.5f)*0.5f - 0.5f + offs[p*2+1];
            float x0f = floorf(ix), y0f = floorf(iy);
            float wx1 = ix - x0f, wy1 = iy - y0f;
            int x0 = (int)x0f, y0 = (int)y0f;
            float vx0 = (x0   >= 0 && x0   <= WI-1) ? 1.f : 0.f;
            float vx1 = (x0+1 >= 0 && x0+1 <= WI-1) ? 1.f : 0.f;
            float vy0 = (y0   >= 0 && y0   <= HI-1) ? 1.f : 0.f;
            float vy1 = (y0+1 >= 0 && y0+1 <= HI-1) ? 1.f : 0.f;
            int xi0 = min(max(x0,   0), WI-1), xi1 = min(max(x0+1, 0), WI-1);
            int yi0 = min(max(y0,   0), HI-1), yi1 = min(max(y0+1, 0), HI-1);
            float w00 = (1.f-wy1)*(1.f-wx1)*vy0*vx0;
            float w01 = (1.f-wy1)*wx1*vy0*vx1;
            float w10 = wy1*(1.f-wx1)*vy1*vx0;
            float w11 = wy1*wx1*vy1*vx1;
            int b00 = yi0*WI + xi0, b01 = yi0*WI + xi1;
            int b10 = yi1*WI + xi0, b11 = yi1*WI + xi1;
            #pragma unroll 4
            for (int c = 0; c < CC; c++) {
                const float* xc = x + c*(HI*WI);
                tile[c*TS + t] = w00*__ldg(xc+b00) + w01*__ldg(xc+b01)
                               + w10*__ldg(xc+b10) + w11*__ldg(xc+b11);
            }
        }
    }
    __syncthreads();

    int oy = blockIdx.y*8 + ty, ox = blockIdx.x*32 + tx;

    int yfl = (oy == 0 || oy == HO-1) ? 1 : 0;
    int xfl = (ox == 0 || ox == WO-1) ? 1 : 0;
    const float* gY = wcls + (yfl + 2*xfl)*1125;

    float acc[32];
    const float* ctr = tile + (ty+2)*36 + (tx+2);
    #pragma unroll
    for (int d = 0; d < CC; d++) acc[d] = ctr[d*TS];   // residual (+fea)
    acc[31] = 0.f;

    #pragma unroll 1
    for (int sy = 0; sy < 5; sy++) {
        #pragma unroll 1
        for (int sx = 0; sx < 5; sx++) {
            int t0 = sy*5 + sx;
            const float* tp = tile + (ty+sy)*36 + (tx+sx);
            float v[CC];
            #pragma unroll
            for (int d = 0; d < CC; d++) v[d] = tp[d*TS];

            #pragma unroll
            for (int sz = 0; sz < 9; sz++) {
                float gv = gY[2*225 + sz*25 + t0];
                #pragma unroll
                for (int d = 2; d <= 28; d++) {
                    int src = d + sz - 4;
                    if (src >= 0 && src < CC) acc[d] += gv * v[src];
                }
            }
            #pragma unroll
            for (int sz = 4; sz < 9; sz++)
                acc[0] += gY[0*225 + sz*25 + t0] * v[sz-4];
            #pragma unroll
            for (int sz = 3; sz < 9; sz++)
                acc[1] += gY[1*225 + sz*25 + t0] * v[sz-3];
            #pragma unroll
            for (int sz = 0; sz < 6; sz++)
                acc[29] += gY[3*225 + sz*25 + t0] * v[25+sz];
            #pragma unroll
            for (int sz = 0; sz < 5; sz++)
                acc[30] += gY[4*225 + sz*25 + t0] * v[26+sz];
        }
    }

    // per-pixel channel mix + fea0 (float4 reads of padded M rows)
    const float* M = Mps + (((oy & 1) << 1) | (ox & 1))*(31*MROW);
    int pix = oy*WO + ox;
    #pragma unroll 1
    for (int ii = 0; ii < 30; ii += 2) {
        const float* M0 = M + ii*MROW;
        const float* M1 = M0 + MROW;
        float s00 = 0.f, s01 = 0.f, s10 = 0.f, s11 = 0.f;
        #pragma unroll
        for (int jc = 0; jc < 8; jc += 2) {
            float4 a0 = *(const float4*)(M0 + jc*4);
            float4 b0 = *(const float4*)(M0 + jc*4 + 4);
            float4 a1 = *(const float4*)(M1 + jc*4);
            float4 b1 = *(const float4*)(M1 + jc*4 + 4);
            int j0 = jc*4;
            s00 += a0.x*acc[j0+0] + a0.y*acc[j0+1] + a0.z*acc[j0+2] + a0.w*acc[j0+3];
            s01 += b0.x*acc[j0+4] + b0.y*acc[j0+5] + b0.z*acc[j0+6] + b0.w*acc[j0+7];
            s10 += a1.x*acc[j0+0] + a1.y*acc[j0+1] + a1.z*acc[j0+2] + a1.w*acc[j0+3];
            s11 += b1.x*acc[j0+4] + b1.y*acc[j0+5] + b1.z*acc[j0+6] + b1.w*acc[j0+7];
        }
        out[ii*NPIX + pix]     = ctr[ii*TS]     + (s00 + s01);
        out[(ii+1)*NPIX + pix] = ctr[(ii+1)*TS] + (s10 + s11);
    }
    {
        const float* M0 = M + 30*MROW;
        float s0 = 0.f, s1 = 0.f;
        #pragma unroll
        for (int jc = 0; jc < 8; jc += 2) {
            float4 a0 = *(const float4*)(M0 + jc*4);
            float4 b0 = *(const float4*)(M0 + jc*4 + 4);
            int j0 = jc*4;
            s0 += a0.x*acc[j0+0] + a0.y*acc[j0+1] + a0.z*acc[j0+2] + a0.w*acc[j0+3];
            s1 += b0.x*acc[j0+4] + b0.y*acc[j0+5] + b0.z*acc[j0+6] + b0.w*acc[j0+7];
        }
        out[30*NPIX + pix] = ctr[30*TS] + (s0 + s1);
    }
}

// ============================ launch ============================
extern "C" void kernel_launch(void* const* d_in, const int* in_sizes, int n_in,
                              void* d_out, int out_size)
{
    const float* x   = (const float*)d_in[0];
    // d_in[1] = scale (always 2; parity tables assume it)
    const float* WE  = (const float*)d_in[2];
    const float* WC  = (const float*)d_in[3];
    const float* W2  = (const float*)d_in[4];
    const float* bw1 = (const float*)d_in[5];
    const float* bb1 = (const float*)d_in[6];
    const float* bw2 = (const float*)d_in[7];
    const float* bb2 = (const float*)d_in[8];
    const float* r2w = (const float*)d_in[9];
    const float* r2b = (const float*)d_in[10];
    const float* ow  = (const float*)d_in[11];
    const float* ob  = (const float*)d_in[12];
    const float* l1w = (const float*)d_in[13];
    const float* l1b = (const float*)d_in[14];
    const float* l2w = (const float*)d_in[15];
    const float* l2b = (const float*)d_in[16];
    float* out = (float*)d_out;

    static int smem_set = 0;
    if (!smem_set) {
        cudaFuncSetAttribute(kall, cudaFuncAttributeMaxDynamicSharedMemorySize,
                             SMEM_F * (int)sizeof(float));
        smem_set = 1;
    }

    kall<<<dim3(WO/32, HO/8), dim3(32, 8), SMEM_F*(int)sizeof(float)>>>(
        x, WE, WC, W2, bw1, bb1, bw2, bb2,
        r2w, r2b, ow, ob, l1w, l1b, l2w, l2b, out);
}

// round 9
// speedup vs baseline: 1.2490x; 1.2490x over previous
#include <cuda_runtime.h>
#include <math.h>

#define CC 31
#define HO 256
#define WO 256
#define NPIX (HO*WO)          // 65536
#define HI 128
#define WI 128

typedef unsigned long long ull;

__device__ __forceinline__ ull pk2(float lo, float hi) {
    ull r; asm("mov.b64 %0,{%1,%2};" : "=l"(r) : "f"(lo), "f"(hi)); return r;
}
__device__ __forceinline__ void fma2(ull& d, ull a, ull b) {
    asm("fma.rn.f32x2 %0,%1,%2,%0;" : "+l"(d) : "l"(a), "l"(b));
}
__device__ __forceinline__ float2 upk(ull v) {
    float2 r; asm("mov.b64 {%0,%1},%2;" : "=f"(r.x), "=f"(r.y) : "l"(v)); return r;
}

// ---------------- static device scratch ----------------
__device__ float d_gcls[5*3*3*225]; // 45 boundary-class composed 9x5x5 kernels
__device__ float d_offp[8];         // per-parity offsets (p = (i&1)*2 | (j&1))
__device__ float d_Mp[4*961];       // per-parity 31x31 mixing matrices

// ============================ k0: all precompute, 49 blocks, redundant ============================
__global__ __launch_bounds__(256) void k0(
    const float* __restrict__ WE,  // (4,32,1,5,3,3) = 4*1440
    const float* __restrict__ WC,
    const float* __restrict__ W2,  // (4,31,31)
    const float* __restrict__ bw1, const float* __restrict__ bb1,
    const float* __restrict__ bw2, const float* __restrict__ bb2,
    const float* __restrict__ r2w, const float* __restrict__ r2b,
    const float* __restrict__ ow,  const float* __restrict__ ob,
    const float* __restrict__ l1w, const float* __restrict__ l1b,
    const float* __restrict__ l2w, const float* __restrict__ l2b)
{
    __shared__ float s_bw2[4096];
    __shared__ float wem[1440], wcm[1440], G2s[2025];
    __shared__ float s_bw1[192], s_bb1[64], s_bb2[64];
    __shared__ float s_r2w[256], s_r2b[4], s_ow[128], s_ob[2];
    __shared__ float s_l1w[128], s_l1b[64], s_l2w[256], s_l2b[4];
    __shared__ float e1s[4][64], e2s[4][64];
    __shared__ float h1s[2][64], lgs[2][4];
    __shared__ float r2s[4][4], rsum_s[4], offs_s[8];

    int tid = threadIdx.x;
    int bid = blockIdx.x;

    // stage
    for (int t = tid; t < 4096; t += 256) s_bw2[t] = bw2[t];
    for (int t = tid; t < 192;  t += 256) s_bw1[t] = bw1[t];
    for (int t = tid; t < 64;   t += 256) { s_bb1[t] = bb1[t]; s_bb2[t] = bb2[t];
                                            s_l1b[t] = l1b[t]; }
    for (int t = tid; t < 256;  t += 256) { s_r2w[t] = r2w[t]; s_l2w[t] = l2w[t]; }
    for (int t = tid; t < 128;  t += 256) { s_ow[t] = ow[t]; s_l1w[t] = l1w[t]; }
    if (tid < 4) { s_r2b[tid] = r2b[tid]; s_l2b[tid] = l2b[tid]; }
    if (tid < 2) s_ob[tid] = ob[tid];
    __syncthreads();

    // MLP layer1 + routing h1
    {
        int p = tid >> 6, o = tid & 63;
        float ch = (p & 2) ? 0.25f : -0.25f;
        float cw = (p & 1) ? 0.25f : -0.25f;
        float a = s_bw1[o*3+0]*0.5f + s_bw1[o*3+1]*ch + s_bw1[o*3+2]*cw + s_bb1[o];
        e1s[p][o] = a > 0.f ? a : 0.f;
    }
    if (tid < 128) {
        int r = tid >> 6, o = tid & 63;
        float chr = r ? 0.25f : -0.25f;
        float a = s_l1w[o*2+0]*0.5f + s_l1w[o*2+1]*chr + s_l1b[o];
        h1s[r][o] = a > 0.f ? a : 0.f;
    }
    __syncthreads();

    // layer2 + routing logits
    {
        int p = tid >> 6, o = tid & 63;
        float a = s_bb2[o];
        #pragma unroll 8
        for (int i = 0; i < 64; i++) a += s_bw2[o*64+i]*e1s[p][i];
        e2s[p][o] = a > 0.f ? a : 0.f;
    }
    if (tid < 8) {
        int r = tid >> 2, e = tid & 3;
        float a = s_l2b[e];
        #pragma unroll 8
        for (int o = 0; o < 64; o++) a += s_l2w[e*64+o]*h1s[r][o];
        lgs[r][e] = a;
    }
    __syncthreads();

    // heads + rsum
    if (tid < 24) {
        int p = tid / 6, u = tid % 6;
        if (u < 2) {
            float a = s_ob[u];
            for (int i = 0; i < 64; i++) a += s_ow[u*64+i]*e2s[p][i];
            offs_s[p*2+u] = a;
        } else {
            int e = u - 2;
            float a = s_r2b[e];
            for (int i = 0; i < 64; i++) a += s_r2w[e*64+i]*e2s[p][i];
            r2s[p][e] = 1.f/(1.f+expf(-a));
        }
    }
    if (tid >= 32 && tid < 36) {
        int e = tid - 32;
        float rsv = 0.f;
        #pragma unroll
        for (int r = 0; r < 2; r++) {
            float m = fmaxf(fmaxf(lgs[r][0], lgs[r][1]), fmaxf(lgs[r][2], lgs[r][3]));
            float s = 0.f;
            #pragma unroll
            for (int j = 0; j < 4; j++) s += expf(lgs[r][j]-m);
            rsv += expf(lgs[r][e]-m)/s;
        }
        rsum_s[e] = rsv;
    }
    __syncthreads();

    if (bid < 45) {
        // rsum-mixed conv weights
        float r0 = rsum_s[0], r1 = rsum_s[1], r2 = rsum_s[2], r3 = rsum_s[3];
        for (int idx = tid; idx < 32*45; idx += 256) {
            wem[idx] = r0*WE[idx] + r1*WE[1440+idx] + r2*WE[2880+idx] + r3*WE[4320+idx];
            wcm[idx] = r0*WC[idx] + r1*WC[1440+idx] + r2*WC[2880+idx] + r3*WC[4320+idx];
        }
        __syncthreads();

        // G2[q][r] = sum_k wcm[k][q]*wem[k][r]
        for (int idx = tid; idx < 45*45; idx += 256) {
            int q = idx / 45, r = idx % 45;
            float a0 = 0.f, a1 = 0.f;
            #pragma unroll
            for (int k = 0; k < 32; k += 2) {
                a0 += wcm[k*45+q]*wem[k*45+r];
                a1 += wcm[(k+1)*45+q]*wem[(k+1)*45+r];
            }
            G2s[idx] = a0 + a1;
        }
        __syncthreads();

        // this block's boundary class (tight bounds)
        if (tid < 225) {
            // zc ranges; y/x class ranges
            const int qzl_t[5] = {2,1,0,0,0}, qzh_t[5] = {4,4,4,3,2};
            const int q3l_t[3] = {0,1,0},     q3h_t[3] = {2,2,1};
            int cls = bid;
            int zc = cls / 9, yc = (cls % 9) / 3, xc = cls % 3;
            int s = tid;
            int sz = s / 25, sy = (s % 25) / 5, sx = s % 5;
            int qzl = max(qzl_t[zc], sz-4), qzh = min(qzh_t[zc], sz);
            int qyl = max(q3l_t[yc], sy-2), qyh = min(q3h_t[yc], sy);
            int qxl = max(q3l_t[xc], sx-2), qxh = min(q3h_t[xc], sx);
            float acc = 0.f;
            for (int qz = qzl; qz <= qzh; qz++) {
                const float* Gz = G2s + qz*9*45 + (sz-qz)*9;
                for (int qy = qyl; qy <= qyh; qy++) {
                    const float* Gy = Gz + qy*3*45 + (sy-qy)*3;
                    for (int qx = qxl; qx <= qxh; qx++)
                        acc += Gy[qx*45 + (sx-qx)];
                }
            }
            d_gcls[cls*225 + s] = acc;
        }
    } else {
        int p = bid - 45;
        float r0 = r2s[p][0], r1 = r2s[p][1], r2 = r2s[p][2], r3 = r2s[p][3];
        for (int ij = tid; ij < 961; ij += 256)
            d_Mp[p*961 + ij] = r0*W2[ij] + r1*W2[961+ij] + r2*W2[2*961+ij] + r3*W2[3*961+ij];
        if (p == 0 && tid < 8) d_offp[tid] = offs_s[tid];
    }
}

// ============================ fused: bilinear + packed conv + residual + mix ============================
// depth-contiguous tile: tile[(yy*36+xx)*34 + d], d in [0,31], pad stride 34.
#define NT    432             // 12*36 taps
#define DSTR  34
#define TILE_F (NT*DSTR)      // 14688
#define WCLS_F (4*5*225)      // 4500
#define MROW   32
#define MPS_F  (4*31*MROW)    // 3968
#define SMEM_F (TILE_F + WCLS_F + MPS_F + 8)

__global__ __launch_bounds__(256, 2) void kfused(const float* __restrict__ x,
                                                 float* __restrict__ out)
{
    extern __shared__ float sm[];
    float* tile = sm;
    float* wcls = sm + TILE_F;
    float* Mps  = sm + TILE_F + WCLS_F;
    float* offs = Mps + MPS_F;

    int tx = threadIdx.x, ty = threadIdx.y;
    int tid = ty*32 + tx;
    int gx0 = blockIdx.x*32 - 2, gy0 = blockIdx.y*8 - 2;

    if (tid < 8) offs[tid] = d_offp[tid];
    int oylo = blockIdx.y*8, oxlo = blockIdx.x*32;
    int yec = (oylo == 0) ? 1 : ((oylo + 7 >= HO-1) ? 2 : 0);
    int xec = (oxlo == 0) ? 1 : ((oxlo + 31 >= WO-1) ? 2 : 0);

    for (int t = tid; t < WCLS_F; t += 256) {
        int slot = t / 1125, r = t % 1125;
        int ys = (slot & 1) ? yec : 0;
        int xs = (slot & 2) ? xec : 0;
        int zc = r / 225;
        wcls[t] = d_gcls[((zc*3 + ys)*3 + xs)*225 + (r % 225)];
    }
    for (int t = tid; t < MPS_F; t += 256) {
        int p = t / (31*MROW), r = t % (31*MROW);
        int ii = r / MROW, jj = r % MROW;
        Mps[t] = (jj < 31) ? d_Mp[p*961 + ii*31 + jj] : 0.f;
    }
    __syncthreads();

    // ---- bilinear halo tile from x (depth-contiguous writes) ----
    for (int t = tid; t < NT; t += 256) {
        int yy = t / 36, xx = t % 36;
        int gy = gy0 + yy, gx = gx0 + xx;
        float* dst = tile + t*DSTR;
        if (gy < 0 || gy >= HO || gx < 0 || gx >= WO) {
            #pragma unroll 8
            for (int c = 0; c < 32; c++) dst[c] = 0.f;
        } else {
            int p = ((gy & 1) << 1) | (gx & 1);
            float ix = (gx + 0.5f)*0.5f - 0.5f + offs[p*2+0];
            float iy = (gy + 0.5f)*0.5f - 0.5f + offs[p*2+1];
            float x0f = floorf(ix), y0f = floorf(iy);
            float wx1 = ix - x0f, wy1 = iy - y0f;
            int x0 = (int)x0f, y0 = (int)y0f;
            float vx0 = (x0   >= 0 && x0   <= WI-1) ? 1.f : 0.f;
            float vx1 = (x0+1 >= 0 && x0+1 <= WI-1) ? 1.f : 0.f;
            float vy0 = (y0   >= 0 && y0   <= HI-1) ? 1.f : 0.f;
            float vy1 = (y0+1 >= 0 && y0+1 <= HI-1) ? 1.f : 0.f;
            int xi0 = min(max(x0,   0), WI-1), xi1 = min(max(x0+1, 0), WI-1);
            int yi0 = min(max(y0,   0), HI-1), yi1 = min(max(y0+1, 0), HI-1);
            float w00 = (1.f-wy1)*(1.f-wx1)*vy0*vx0;
            float w01 = (1.f-wy1)*wx1*vy0*vx1;
            float w10 = wy1*(1.f-wx1)*vy1*vx0;
            float w11 = wy1*wx1*vy1*vx1;
            int b00 = yi0*WI + xi0, b01 = yi0*WI + xi1;
            int b10 = yi1*WI + xi0, b11 = yi1*WI + xi1;
            #pragma unroll 4
            for (int c = 0; c < CC; c++) {
                const float* xc = x + c*(HI*WI);
                dst[c] = w00*__ldg(xc+b00) + w01*__ldg(xc+b01)
                       + w10*__ldg(xc+b10) + w11*__ldg(xc+b11);
            }
            dst[31] = 0.f;
        }
    }
    __syncthreads();

    int oy = blockIdx.y*8 + ty, ox = blockIdx.x*32 + tx;
    int yfl = (oy == 0 || oy == HO-1) ? 1 : 0;
    int xfl = (ox == 0 || ox == WO-1) ? 1 : 0;
    const float* gY = wcls + (yfl + 2*xfl)*1125;

    // dual-parity packed accumulators
    ull accE[16], accO[15];
    float acc0x = 0.f;
    const float* ctr = tile + ((ty+2)*36 + (tx+2))*DSTR;
    #pragma unroll
    for (int k = 0; k < 16; k++) accE[k] = *(const ull*)(ctr + 2*k);   // residual init
    #pragma unroll
    for (int k = 0; k < 15; k++) accO[k] = 0ULL;

    #pragma unroll 1
    for (int sy = 0; sy < 5; sy++) {
        #pragma unroll 1
        for (int sx = 0; sx < 5; sx++) {
            const float* tp = tile + ((ty+sy)*36 + (tx+sx))*DSTR;
            const float* gt = gY + sy*5 + sx;   // + zc*225 + sz*25
            ull ve[20];
            ve[0] = 0ULL; ve[1] = 0ULL; ve[18] = 0ULL; ve[19] = 0ULL;
            #pragma unroll
            for (int m = 0; m < 16; m++) ve[m+2] = *(const ull*)(tp + 2*m);

            // ---- even sz (accE: pairs (2k,2k+1)) ----
            #pragma unroll
            for (int szh = 0; szh < 5; szh++) {
                const int sz = 2*szh;
                float gi = gt[450 + sz*25];
                ull wII = pk2(gi, gi);
                if (szh >= 2) {                        // sz>=4: pair (d0,d1)=(g0,g1)
                    fma2(accE[0], ve[szh], pk2(gt[sz*25], gt[225 + sz*25]));
                }
                #pragma unroll
                for (int k = 1; k <= 13; k++) {
                    if (!(k == 1 && szh == 0))         // ve[1]=0
                        fma2(accE[k], ve[k+szh], wII);
                }
                if (szh <= 2) {                        // sz<=4: (gi,g3)
                    fma2(accE[14], ve[14+szh], pk2(gi, gt[675 + sz*25]));
                } else if (szh == 3) {                 // sz=6: (gi,0)
                    fma2(accE[14], ve[17], pk2(gi, 0.f));
                }                                      // sz=8: v zero, skip
                if (szh <= 2) {                        // sz<=4: (g4,0)
                    fma2(accE[15], ve[15+szh], pk2(gt[900 + sz*25], 0.f));
                }
            }
            // ---- odd sz (accO: pairs (2k+1,2k+2)) ----
            #pragma unroll
            for (int szh = 0; szh < 4; szh++) {
                const int sz = 2*szh + 1;
                const int h = szh + 1;
                float gi = gt[450 + sz*25];
                ull wII = pk2(gi, gi);
                if (sz >= 3) {                         // pair (d1,d2)=(g1,gi); sz=1: v zero
                    fma2(accO[0], ve[h], pk2(gt[225 + sz*25], gi));
                }
                #pragma unroll
                for (int k = 1; k <= 13; k++)
                    fma2(accO[k], ve[k+h], wII);
                if (sz <= 3) {                         // (g3,g4)
                    fma2(accO[14], ve[14+h], pk2(gt[675 + sz*25], gt[900 + sz*25]));
                } else if (sz == 5) {                  // (g3,0)
                    fma2(accO[14], ve[17], pk2(gt[675 + sz*25], 0.f));
                }                                      // sz=7: skip
                if (sz >= 5) {                         // d0 odd-sz scalar fixup
                    acc0x += gt[sz*25] * upk(ve[szh]).y;   // v[sz-4]
                }
            }
        }
    }

    // combine
    float a[32];
    #pragma unroll
    for (int k = 0; k < 16; k++) { float2 e = upk(accE[k]); a[2*k] = e.x; a[2*k+1] = e.y; }
    #pragma unroll
    for (int k = 0; k < 15; k++) { float2 o = upk(accO[k]); a[2*k+1] += o.x; a[2*k+2] += o.y; }
    a[0] += acc0x;
    a[31] = 0.f;

    // per-pixel channel mix + fea0 (float4 reads of padded M rows)
    const float* M = Mps + (((oy & 1) << 1) | (ox & 1))*(31*MROW);
    int pix = oy*WO + ox;
    #pragma unroll 1
    for (int ii = 0; ii < 30; ii += 2) {
        const float* M0 = M + ii*MROW;
        const float* M1 = M0 + MROW;
        float s00 = 0.f, s01 = 0.f, s10 = 0.f, s11 = 0.f;
        #pragma unroll
        for (int jc = 0; jc < 8; jc += 2) {
            float4 a0 = *(const float4*)(M0 + jc*4);
            float4 b0 = *(const float4*)(M0 + jc*4 + 4);
            float4 a1 = *(const float4*)(M1 + jc*4);
            float4 b1 = *(const float4*)(M1 + jc*4 + 4);
            int j0 = jc*4;
            s00 += a0.x*a[j0+0] + a0.y*a[j0+1] + a0.z*a[j0+2] + a0.w*a[j0+3];
            s01 += b0.x*a[j0+4] + b0.y*a[j0+5] + b0.z*a[j0+6] + b0.w*a[j0+7];
            s10 += a1.x*a[j0+0] + a1.y*a[j0+1] + a1.z*a[j0+2] + a1.w*a[j0+3];
            s11 += b1.x*a[j0+4] + b1.y*a[j0+5] + b1.z*a[j0+6] + b1.w*a[j0+7];
        }
        out[ii*NPIX + pix]     = ctr[ii]   + (s00 + s01);
        out[(ii+1)*NPIX + pix] = ctr[ii+1] + (s10 + s11);
    }
    {
        const float* M0 = M + 30*MROW;
        float s0 = 0.f, s1 = 0.f;
        #pragma unroll
        for (int jc = 0; jc < 8; jc += 2) {
            float4 a0 = *(const float4*)(M0 + jc*4);
            float4 b0 = *(const float4*)(M0 + jc*4 + 4);
            int j0 = jc*4;
            s0 += a0.x*a[j0+0] + a0.y*a[j0+1] + a0.z*a[j0+2] + a0.w*a[j0+3];
            s1 += b0.x*a[j0+4] + b0.y*a[j0+5] + b0.z*a[j0+6] + b0.w*a[j0+7];
        }
        out[30*NPIX + pix] = ctr[30] + (s0 + s1);
    }
}

// ============================ launch ============================
extern "C" void kernel_launch(void* const* d_in, const int* in_sizes, int n_in,
                              void* d_out, int out_size)
{
    const float* x   = (const float*)d_in[0];
    // d_in[1] = scale (always 2; parity tables assume it)
    const float* WE  = (const float*)d_in[2];
    const float* WC  = (const float*)d_in[3];
    const float* W2  = (const float*)d_in[4];
    const float* bw1 = (const float*)d_in[5];
    const float* bb1 = (const float*)d_in[6];
    const float* bw2 = (const float*)d_in[7];
    const float* bb2 = (const float*)d_in[8];
    const float* r2w = (const float*)d_in[9];
    const float* r2b = (const float*)d_in[10];
    const float* ow  = (const float*)d_in[11];
    const float* ob  = (const float*)d_in[12];
    const float* l1w = (const float*)d_in[13];
    const float* l1b = (const float*)d_in[14];
    const float* l2w = (const float*)d_in[15];
    const float* l2b = (const float*)d_in[16];
    float* out = (float*)d_out;

    static int smem_set = 0;
    if (!smem_set) {
        cudaFuncSetAttribute(kfused, cudaFuncAttributeMaxDynamicSharedMemorySize,
                             SMEM_F * (int)sizeof(float));
        smem_set = 1;
    }

    k0<<<49, 256>>>(WE, WC, W2, bw1, bb1, bw2, bb2,
                    r2w, r2b, ow, ob, l1w, l1b, l2w, l2b);
    kfused<<<dim3(WO/32, HO/8), dim3(32, 8), SMEM_F*(int)sizeof(float)>>>(x, out);
}